// round 5
// baseline (speedup 1.0000x reference)
#include <cuda_runtime.h>
#include <math.h>

// Problem constants
#define kB 2
#define kS 2048
#define kE 1024
#define kH 16
#define kD 64
#define kBH (kB * kH)
#define kScale 0.125f
#define kLN1e4 9.210340371976184f

// Scratch (device globals: allocation-free)
static __device__ float g_q[kBH * kS * kD];    // [bh][s][d]  (tf32, rope+scale)
static __device__ float g_k[kBH * kS * kD];    // [bh][s][d]  (tf32, rope)
static __device__ float g_vt[kBH * kD * kS];   // [bh][d][s]  (tf32, transposed V)
static __device__ float g_ctx[kB * kS * kE];   // [b][s][h*64+d]

// ---------------- helpers ----------------
__device__ __forceinline__ unsigned f2tf(float x) {
    unsigned u;
    asm("cvt.rna.tf32.f32 %0, %1;" : "=r"(u) : "f"(x));
    return u;
}
__device__ __forceinline__ float tf32r(float x) { return __uint_as_float(f2tf(x)); }
__device__ __forceinline__ unsigned fbits(float x) { return __float_as_uint(x); }
__device__ __forceinline__ unsigned smem_u32(const void* p) {
    unsigned r;
    asm("{ .reg .u64 t; cvta.to.shared.u64 t, %1; cvt.u32.u64 %0, t; }"
        : "=r"(r) : "l"(p));
    return r;
}
__device__ __forceinline__ void ldsm4(unsigned* f, unsigned addr) {
    asm volatile("ldmatrix.sync.aligned.m8n8.x4.shared.b16 {%0,%1,%2,%3}, [%4];"
                 : "=r"(f[0]), "=r"(f[1]), "=r"(f[2]), "=r"(f[3]) : "r"(addr));
}
// D(16x8,f32) += A(16x8,tf32) * B(8x8,tf32)
__device__ __forceinline__ void mma8(float* c, const unsigned* a, const unsigned* b) {
    asm volatile(
        "mma.sync.aligned.m16n8k8.row.col.f32.tf32.tf32.f32 "
        "{%0,%1,%2,%3}, {%4,%5,%6,%7}, {%8,%9}, {%0,%1,%2,%3};"
        : "+f"(c[0]), "+f"(c[1]), "+f"(c[2]), "+f"(c[3])
        : "r"(a[0]), "r"(a[1]), "r"(a[2]), "r"(a[3]), "r"(b[0]), "r"(b[1]));
}

// ---------------- Tensor-core GEMM: out[m,n] = sum_k A[m,k]*W[n,k] ----------------
// BM=128, BN=128, BK=16, double-buffered. 256 threads = 8 warps (2m x 4n),
// warp tile 64x32.  mode 0: A=query, W=w_qkv -> g_q/g_k/g_vt (RoPE fused).
// mode 1: A=g_ctx, W=w_out -> out.
#define GBK 16
#define GPAD 20
__global__ __launch_bounds__(256) void gemm_tc(const float* __restrict__ Ain,
                                               const float* __restrict__ W,
                                               float* __restrict__ out, int mode) {
    __shared__ float As[2][128][GPAD];
    __shared__ float Ws[2][128][GPAD];
    const float* A = (mode == 1) ? g_ctx : Ain;

    const int t = threadIdx.x;
    const int w = t >> 5, lane = t & 31;
    const int r = lane >> 2, q = lane & 3;
    const int wm = w >> 2, wn = w & 3;
    const int m0 = blockIdx.x * 128;
    const int n0 = blockIdx.y * 128;

    const int lrow = t >> 2;        // 0..63
    const int lcol = 4 * (t & 3);   // 0,4,8,12

    float c[4][4][4];
#pragma unroll
    for (int i = 0; i < 4; i++)
#pragma unroll
        for (int j = 0; j < 4; j++)
#pragma unroll
            for (int v = 0; v < 4; v++) c[i][j][v] = 0.f;

    const float* Arow0 = A + (size_t)(m0 + lrow) * kE + lcol;
    const float* Arow1 = A + (size_t)(m0 + lrow + 64) * kE + lcol;
    const float* Wrow0 = W + (size_t)(n0 + lrow) * kE + lcol;
    const float* Wrow1 = W + (size_t)(n0 + lrow + 64) * kE + lcol;

    float4 pa0 = *(const float4*)Arow0;
    float4 pa1 = *(const float4*)Arow1;
    float4 pw0 = *(const float4*)Wrow0;
    float4 pw1 = *(const float4*)Wrow1;

    *(float4*)&As[0][lrow][lcol] =
        make_float4(tf32r(pa0.x), tf32r(pa0.y), tf32r(pa0.z), tf32r(pa0.w));
    *(float4*)&As[0][lrow + 64][lcol] =
        make_float4(tf32r(pa1.x), tf32r(pa1.y), tf32r(pa1.z), tf32r(pa1.w));
    *(float4*)&Ws[0][lrow][lcol] =
        make_float4(tf32r(pw0.x), tf32r(pw0.y), tf32r(pw0.z), tf32r(pw0.w));
    *(float4*)&Ws[0][lrow + 64][lcol] =
        make_float4(tf32r(pw1.x), tf32r(pw1.y), tf32r(pw1.z), tf32r(pw1.w));
    __syncthreads();

    const unsigned aBase = smem_u32(&As[0][0][0]);
    const unsigned wBase = smem_u32(&Ws[0][0][0]);
    const unsigned stageSz = 128 * GPAD * 4;
    unsigned aoff[4], woff[2];
#pragma unroll
    for (int mt = 0; mt < 4; mt++)
        aoff[mt] = aBase +
                   ((wm * 64 + mt * 16 + (lane & 15)) * GPAD + (lane >> 4) * 4) * 4;
#pragma unroll
    for (int ng = 0; ng < 2; ng++)
        woff[ng] = wBase + ((wn * 32 + ng * 16 + (lane & 7) + ((lane >> 4) & 1) * 8) *
                                GPAD +
                            ((lane >> 3) & 1) * 4) *
                               4;

    const int NIT = kE / GBK;  // 64
    for (int it = 0; it < NIT; it++) {
        const int cur = it & 1;
        if (it + 1 < NIT) {
            int k0 = (it + 1) * GBK;
            pa0 = *(const float4*)(Arow0 + k0);
            pa1 = *(const float4*)(Arow1 + k0);
            pw0 = *(const float4*)(Wrow0 + k0);
            pw1 = *(const float4*)(Wrow1 + k0);
        }
        const unsigned aS = cur ? stageSz : 0u;
        const unsigned wS = cur ? stageSz : 0u;
#pragma unroll
        for (int kk = 0; kk < 2; kk++) {
            unsigned af[4][4], bf[2][4];
#pragma unroll
            for (int mt = 0; mt < 4; mt++) ldsm4(af[mt], aoff[mt] + aS + kk * 32);
#pragma unroll
            for (int ng = 0; ng < 2; ng++) ldsm4(bf[ng], woff[ng] + wS + kk * 32);
#pragma unroll
            for (int mt = 0; mt < 4; mt++)
#pragma unroll
                for (int ng = 0; ng < 2; ng++) {
                    mma8(c[mt][2 * ng], af[mt], &bf[ng][0]);
                    mma8(c[mt][2 * ng + 1], af[mt], &bf[ng][2]);
                }
        }
        if (it + 1 < NIT) {
            const int nxt = cur ^ 1;
            *(float4*)&As[nxt][lrow][lcol] =
                make_float4(tf32r(pa0.x), tf32r(pa0.y), tf32r(pa0.z), tf32r(pa0.w));
            *(float4*)&As[nxt][lrow + 64][lcol] =
                make_float4(tf32r(pa1.x), tf32r(pa1.y), tf32r(pa1.z), tf32r(pa1.w));
            *(float4*)&Ws[nxt][lrow][lcol] =
                make_float4(tf32r(pw0.x), tf32r(pw0.y), tf32r(pw0.z), tf32r(pw0.w));
            *(float4*)&Ws[nxt][lrow + 64][lcol] =
                make_float4(tf32r(pw1.x), tf32r(pw1.y), tf32r(pw1.z), tf32r(pw1.w));
        }
        __syncthreads();
    }

    // ---------------- epilogue ----------------
    if (mode == 1) {
#pragma unroll
        for (int mt = 0; mt < 4; mt++)
#pragma unroll
            for (int nt = 0; nt < 4; nt++) {
                int mrow = m0 + wm * 64 + mt * 16 + r;
                int col = n0 + wn * 32 + (nt >> 1) * 16 + (nt & 1) * 8 + 2 * q;
                *(float2*)&out[(size_t)mrow * kE + col] =
                    make_float2(c[mt][nt][0], c[mt][nt][1]);
                *(float2*)&out[(size_t)(mrow + 8) * kE + col] =
                    make_float2(c[mt][nt][2], c[mt][nt][3]);
            }
    } else {
        const int which = (n0 >> 10);  // 0=q 1=k 2=v
#pragma unroll
        for (int mt = 0; mt < 4; mt++)
#pragma unroll
            for (int nt = 0; nt < 4; nt++) {
                int mrow = m0 + wm * 64 + mt * 16 + r;
                int n = n0 + wn * 32 + (nt >> 1) * 16 + (nt & 1) * 8 + 2 * q;
                int h = (n >> 6) & 15;
                int dl = n & 63;
                int b = mrow >> 11, s = mrow & (kS - 1);
                int bh = b * kH + h;
                if (which == 2) {
                    size_t base = ((size_t)(bh * kD + dl)) * kS;
                    g_vt[base + s] = tf32r(c[mt][nt][0]);
                    g_vt[base + kS + s] = tf32r(c[mt][nt][1]);
                    g_vt[base + s + 8] = tf32r(c[mt][nt][2]);
                    g_vt[base + kS + s + 8] = tf32r(c[mt][nt][3]);
                } else {
                    int i = dl >> 1;
                    float inv = expf(-(float)i * (kLN1e4 / 32.0f));
                    float sn0, cs0, sn1, cs1;
                    sincosf((float)s * inv, &sn0, &cs0);
                    sincosf((float)(s + 8) * inv, &sn1, &cs1);
                    float y0 = c[mt][nt][0] * cs0 - c[mt][nt][1] * sn0;
                    float y1 = c[mt][nt][0] * sn0 + c[mt][nt][1] * cs0;
                    float z0 = c[mt][nt][2] * cs1 - c[mt][nt][3] * sn1;
                    float z1 = c[mt][nt][2] * sn1 + c[mt][nt][3] * cs1;
                    float* dst;
                    if (which == 0) {
                        y0 *= kScale; y1 *= kScale; z0 *= kScale; z1 *= kScale;
                        dst = g_q;
                    } else {
                        dst = g_k;
                    }
                    size_t base = ((size_t)(bh * kS + s)) * kD + dl;
                    *(float2*)&dst[base] = make_float2(tf32r(y0), tf32r(y1));
                    *(float2*)&dst[base + 8 * kD] = make_float2(tf32r(z0), tf32r(z1));
                }
            }
    }
}

// ---------------- Flash attention: mma.sync tf32, scalar broadcast B-frags ----
// grid: (16 q-tiles, 32 bh). block: 256 threads = 8 warps, warp = 16 q rows
// -> 128 q rows per block. K/V tile = 64.
__global__ __launch_bounds__(256) void attn_tc() {
    __shared__ float Ks[64][68];  // [kv][d]
    __shared__ float Vs[64][68];  // [d][kv]
    const int t = threadIdx.x;
    const int w = t >> 5, lane = t & 31;
    const int r = lane >> 2, q = lane & 3;
    const int bh = blockIdx.y;
    const int q0 = blockIdx.x * 128;
    const float* qb = g_q + ((size_t)bh * kS + q0) * kD;
    const float* kb = g_k + (size_t)bh * kS * kD;
    const float* vtb = g_vt + (size_t)bh * kD * kS;

    // Stage Q (128 rows) in two 64-row halves through Ks; extract scalar frags
    unsigned qa[8][4];
#pragma unroll 1
    for (int half = 0; half < 2; half++) {
        __syncthreads();
        const float4* qsrc = (const float4*)(qb + (size_t)half * 64 * kD);
#pragma unroll
        for (int j = 0; j < 4; j++) {
            int f4i = t + 256 * j;
            *(float4*)&Ks[f4i >> 4][(f4i & 15) * 4] = qsrc[f4i];
        }
        __syncthreads();
        if ((w >> 2) == half) {
            int m = 16 * (w & 3) + r;
#pragma unroll
            for (int kk = 0; kk < 8; kk++) {
                qa[kk][0] = fbits(Ks[m][kk * 8 + q]);
                qa[kk][1] = fbits(Ks[m + 8][kk * 8 + q]);
                qa[kk][2] = fbits(Ks[m][kk * 8 + 4 + q]);
                qa[kk][3] = fbits(Ks[m + 8][kk * 8 + 4 + q]);
            }
        }
    }

    float m0v = -1e30f, m1v = -1e30f, l0 = 0.f, l1 = 0.f;
    float o[8][4];
#pragma unroll
    for (int i = 0; i < 8; i++)
#pragma unroll
        for (int j = 0; j < 4; j++) o[i][j] = 0.f;

    const int src0 = (lane & ~3) | (q >> 1);
    const int src2 = src0 + 2;

    for (int kt = 0; kt < 32; kt++) {
        __syncthreads();
        {
            const float4* ksrc = (const float4*)(kb + (size_t)kt * 64 * kD);
#pragma unroll
            for (int j = 0; j < 4; j++) {
                int f4i = t + 256 * j;
                *(float4*)&Ks[f4i >> 4][(f4i & 15) * 4] = ksrc[f4i];
            }
#pragma unroll
            for (int j = 0; j < 4; j++) {
                int row = (t >> 4) + 16 * j;
                *(float4*)&Vs[row][4 * (t & 15)] =
                    ((const float4*)(vtb + (size_t)row * kS + kt * 64))[t & 15];
            }
        }
        __syncthreads();

        // S = Q K^T  (c[nt] covers cols 8nt + {2q,2q+1}; rows 16w+r / +8)
        float c[8][4];
#pragma unroll
        for (int i = 0; i < 8; i++)
#pragma unroll
            for (int j = 0; j < 4; j++) c[i][j] = 0.f;
#pragma unroll
        for (int kk = 0; kk < 8; kk++) {
#pragma unroll
            for (int nt = 0; nt < 8; nt++) {
                unsigned bf[2];
                bf[0] = fbits(Ks[8 * nt + r][kk * 8 + q]);
                bf[1] = fbits(Ks[8 * nt + r][kk * 8 + 4 + q]);
                mma8(c[nt], qa[kk], bf);
            }
        }

        // online softmax
        float mt0 = -1e30f, mt1 = -1e30f;
#pragma unroll
        for (int nt = 0; nt < 8; nt++) {
            mt0 = fmaxf(mt0, fmaxf(c[nt][0], c[nt][1]));
            mt1 = fmaxf(mt1, fmaxf(c[nt][2], c[nt][3]));
        }
        mt0 = fmaxf(mt0, __shfl_xor_sync(0xffffffffu, mt0, 1));
        mt0 = fmaxf(mt0, __shfl_xor_sync(0xffffffffu, mt0, 2));
        mt1 = fmaxf(mt1, __shfl_xor_sync(0xffffffffu, mt1, 1));
        mt1 = fmaxf(mt1, __shfl_xor_sync(0xffffffffu, mt1, 2));
        float mn0 = fmaxf(m0v, mt0), mn1 = fmaxf(m1v, mt1);
        float cor0 = __expf(m0v - mn0), cor1 = __expf(m1v - mn1);
        m0v = mn0; m1v = mn1;
        float rs0 = 0.f, rs1 = 0.f;
#pragma unroll
        for (int nt = 0; nt < 8; nt++) {
            c[nt][0] = __expf(c[nt][0] - mn0); rs0 += c[nt][0];
            c[nt][1] = __expf(c[nt][1] - mn0); rs0 += c[nt][1];
            c[nt][2] = __expf(c[nt][2] - mn1); rs1 += c[nt][2];
            c[nt][3] = __expf(c[nt][3] - mn1); rs1 += c[nt][3];
        }
        rs0 += __shfl_xor_sync(0xffffffffu, rs0, 1);
        rs0 += __shfl_xor_sync(0xffffffffu, rs0, 2);
        rs1 += __shfl_xor_sync(0xffffffffu, rs1, 1);
        rs1 += __shfl_xor_sync(0xffffffffu, rs1, 2);
        l0 = l0 * cor0 + rs0;
        l1 = l1 * cor1 + rs1;
#pragma unroll
        for (int nt = 0; nt < 8; nt++) {
            o[nt][0] *= cor0; o[nt][1] *= cor0;
            o[nt][2] *= cor1; o[nt][3] *= cor1;
        }

        // O += P V  (P A-frags via intra-quad shuffles)
#pragma unroll
        for (int kk = 0; kk < 8; kk++) {
            float u0 = __shfl_sync(0xffffffffu, c[kk][0], src0);
            float u1 = __shfl_sync(0xffffffffu, c[kk][1], src0);
            float u2 = __shfl_sync(0xffffffffu, c[kk][2], src0);
            float u3 = __shfl_sync(0xffffffffu, c[kk][3], src0);
            float v0 = __shfl_sync(0xffffffffu, c[kk][0], src2);
            float v1 = __shfl_sync(0xffffffffu, c[kk][1], src2);
            float v2 = __shfl_sync(0xffffffffu, c[kk][2], src2);
            float v3 = __shfl_sync(0xffffffffu, c[kk][3], src2);
            unsigned pa[4];
            pa[0] = f2tf((q & 1) ? u1 : u0);
            pa[1] = f2tf((q & 1) ? u3 : u2);
            pa[2] = f2tf((q & 1) ? v1 : v0);
            pa[3] = f2tf((q & 1) ? v3 : v2);
#pragma unroll
            for (int nt = 0; nt < 8; nt++) {
                unsigned bf[2];
                bf[0] = fbits(Vs[8 * nt + r][kk * 8 + q]);
                bf[1] = fbits(Vs[8 * nt + r][kk * 8 + 4 + q]);
                mma8(o[nt], pa, bf);
            }
        }
    }

    // epilogue: normalize and store to ctx [b][s][h*64+d]
    float il0 = 1.f / l0, il1 = 1.f / l1;
    const int b = bh >> 4, h = bh & 15;
    const int row0 = q0 + 16 * w + r;
    float* dst = g_ctx + ((size_t)(b * kS + row0)) * kE + h * kD;
#pragma unroll
    for (int nt = 0; nt < 8; nt++) {
        *(float2*)&dst[8 * nt + 2 * q] =
            make_float2(o[nt][0] * il0, o[nt][1] * il0);
        *(float2*)&dst[8 * kE + 8 * nt + 2 * q] =
            make_float2(o[nt][2] * il1, o[nt][3] * il1);
    }
}

extern "C" void kernel_launch(void* const* d_in, const int* in_sizes, int n_in,
                              void* d_out, int out_size) {
    const float* query = (const float*)d_in[0];
    // d_in[1] (key), d_in[2] (value) are unused by the reference computation
    const float* w_qkv = (const float*)d_in[3];
    const float* w_out = (const float*)d_in[4];
    float* out = (float*)d_out;

    gemm_tc<<<dim3(32, 24), 256>>>(query, w_qkv, nullptr, 0);
    attn_tc<<<dim3(16, 32), 256>>>();
    gemm_tc<<<dim3(32, 8), 256>>>(nullptr, w_out, out, 1);
}

// round 6
// speedup vs baseline: 1.5523x; 1.5523x over previous
#include <cuda_runtime.h>
#include <math.h>

// Problem constants
#define kB 2
#define kS 2048
#define kE 1024
#define kH 16
#define kD 64
#define kBH (kB * kH)
#define kScale 0.125f
#define kLN1e4 9.210340371976184f

// Scratch (device globals: allocation-free)
static __device__ float g_q[kBH * kS * kD];    // [bh][s][d]  (tf32, rope+scale)
static __device__ float g_k[kBH * kS * kD];    // [bh][s][d]  (tf32, rope)
static __device__ float g_vt[kBH * kD * kS];   // [bh][d][s]  (tf32, transposed V)
static __device__ float g_ctx[kB * kS * kE];   // [b][s][h*64+d]

// ---------------- helpers ----------------
__device__ __forceinline__ unsigned f2tf(float x) {
    unsigned u;
    asm("cvt.rna.tf32.f32 %0, %1;" : "=r"(u) : "f"(x));
    return u;
}
__device__ __forceinline__ float tf32r(float x) { return __uint_as_float(f2tf(x)); }
__device__ __forceinline__ unsigned fbits(float x) { return __float_as_uint(x); }
__device__ __forceinline__ unsigned smem_u32(const void* p) {
    unsigned r;
    asm("{ .reg .u64 t; cvta.to.shared.u64 t, %1; cvt.u32.u64 %0, t; }"
        : "=r"(r) : "l"(p));
    return r;
}
__device__ __forceinline__ void ldsm4(unsigned* f, unsigned addr) {
    asm volatile("ldmatrix.sync.aligned.m8n8.x4.shared.b16 {%0,%1,%2,%3}, [%4];"
                 : "=r"(f[0]), "=r"(f[1]), "=r"(f[2]), "=r"(f[3]) : "r"(addr));
}
__device__ __forceinline__ void cp16(void* dst, const void* src) {
    asm volatile("cp.async.cg.shared.global [%0], [%1], 16;" ::
                     "r"(smem_u32(dst)), "l"(src) : "memory");
}
#define CP_COMMIT() asm volatile("cp.async.commit_group;" ::: "memory")
#define CP_WAIT(n) asm volatile("cp.async.wait_group %0;" :: "n"(n) : "memory")

// D(16x8,f32) += A(16x8,tf32) * B(8x8,tf32)
__device__ __forceinline__ void mma8(float* c, const unsigned* a, const unsigned* b) {
    asm volatile(
        "mma.sync.aligned.m16n8k8.row.col.f32.tf32.tf32.f32 "
        "{%0,%1,%2,%3}, {%4,%5,%6,%7}, {%8,%9}, {%0,%1,%2,%3};"
        : "+f"(c[0]), "+f"(c[1]), "+f"(c[2]), "+f"(c[3])
        : "r"(a[0]), "r"(a[1]), "r"(a[2]), "r"(a[3]), "r"(b[0]), "r"(b[1]));
}

// ---------------- Tensor-core GEMM: out[m,n] = sum_k A[m,k]*W[n,k] ----------------
// (unchanged from round 3 — best measured config)
#define GBK 16
#define GPAD 20
__global__ __launch_bounds__(256) void gemm_tc(const float* __restrict__ Ain,
                                               const float* __restrict__ W,
                                               float* __restrict__ out, int mode) {
    __shared__ float As[2][128][GPAD];
    __shared__ float Ws[2][128][GPAD];
    const float* A = (mode == 1) ? g_ctx : Ain;

    const int t = threadIdx.x;
    const int w = t >> 5, lane = t & 31;
    const int r = lane >> 2, q = lane & 3;
    const int wm = w >> 2, wn = w & 3;
    const int m0 = blockIdx.x * 128;
    const int n0 = blockIdx.y * 128;

    const int lrow = t >> 2;
    const int lcol = 4 * (t & 3);

    float c[4][4][4];
#pragma unroll
    for (int i = 0; i < 4; i++)
#pragma unroll
        for (int j = 0; j < 4; j++)
#pragma unroll
            for (int v = 0; v < 4; v++) c[i][j][v] = 0.f;

    const float* Arow0 = A + (size_t)(m0 + lrow) * kE + lcol;
    const float* Arow1 = A + (size_t)(m0 + lrow + 64) * kE + lcol;
    const float* Wrow0 = W + (size_t)(n0 + lrow) * kE + lcol;
    const float* Wrow1 = W + (size_t)(n0 + lrow + 64) * kE + lcol;

    float4 pa0 = *(const float4*)Arow0;
    float4 pa1 = *(const float4*)Arow1;
    float4 pw0 = *(const float4*)Wrow0;
    float4 pw1 = *(const float4*)Wrow1;

    *(float4*)&As[0][lrow][lcol] =
        make_float4(tf32r(pa0.x), tf32r(pa0.y), tf32r(pa0.z), tf32r(pa0.w));
    *(float4*)&As[0][lrow + 64][lcol] =
        make_float4(tf32r(pa1.x), tf32r(pa1.y), tf32r(pa1.z), tf32r(pa1.w));
    *(float4*)&Ws[0][lrow][lcol] =
        make_float4(tf32r(pw0.x), tf32r(pw0.y), tf32r(pw0.z), tf32r(pw0.w));
    *(float4*)&Ws[0][lrow + 64][lcol] =
        make_float4(tf32r(pw1.x), tf32r(pw1.y), tf32r(pw1.z), tf32r(pw1.w));
    __syncthreads();

    const unsigned aBase = smem_u32(&As[0][0][0]);
    const unsigned wBase = smem_u32(&Ws[0][0][0]);
    const unsigned stageSz = 128 * GPAD * 4;
    unsigned aoff[4], woff[2];
#pragma unroll
    for (int mt = 0; mt < 4; mt++)
        aoff[mt] = aBase +
                   ((wm * 64 + mt * 16 + (lane & 15)) * GPAD + (lane >> 4) * 4) * 4;
#pragma unroll
    for (int ng = 0; ng < 2; ng++)
        woff[ng] = wBase + ((wn * 32 + ng * 16 + (lane & 7) + ((lane >> 4) & 1) * 8) *
                                GPAD +
                            ((lane >> 3) & 1) * 4) *
                               4;

    const int NIT = kE / GBK;
    for (int it = 0; it < NIT; it++) {
        const int cur = it & 1;
        if (it + 1 < NIT) {
            int k0 = (it + 1) * GBK;
            pa0 = *(const float4*)(Arow0 + k0);
            pa1 = *(const float4*)(Arow1 + k0);
            pw0 = *(const float4*)(Wrow0 + k0);
            pw1 = *(const float4*)(Wrow1 + k0);
        }
        const unsigned aS = cur ? stageSz : 0u;
        const unsigned wS = cur ? stageSz : 0u;
#pragma unroll
        for (int kk = 0; kk < 2; kk++) {
            unsigned af[4][4], bf[2][4];
#pragma unroll
            for (int mt = 0; mt < 4; mt++) ldsm4(af[mt], aoff[mt] + aS + kk * 32);
#pragma unroll
            for (int ng = 0; ng < 2; ng++) ldsm4(bf[ng], woff[ng] + wS + kk * 32);
#pragma unroll
            for (int mt = 0; mt < 4; mt++)
#pragma unroll
                for (int ng = 0; ng < 2; ng++) {
                    mma8(c[mt][2 * ng], af[mt], &bf[ng][0]);
                    mma8(c[mt][2 * ng + 1], af[mt], &bf[ng][2]);
                }
        }
        if (it + 1 < NIT) {
            const int nxt = cur ^ 1;
            *(float4*)&As[nxt][lrow][lcol] =
                make_float4(tf32r(pa0.x), tf32r(pa0.y), tf32r(pa0.z), tf32r(pa0.w));
            *(float4*)&As[nxt][lrow + 64][lcol] =
                make_float4(tf32r(pa1.x), tf32r(pa1.y), tf32r(pa1.z), tf32r(pa1.w));
            *(float4*)&Ws[nxt][lrow][lcol] =
                make_float4(tf32r(pw0.x), tf32r(pw0.y), tf32r(pw0.z), tf32r(pw0.w));
            *(float4*)&Ws[nxt][lrow + 64][lcol] =
                make_float4(tf32r(pw1.x), tf32r(pw1.y), tf32r(pw1.z), tf32r(pw1.w));
        }
        __syncthreads();
    }

    // ---------------- epilogue ----------------
    if (mode == 1) {
#pragma unroll
        for (int mt = 0; mt < 4; mt++)
#pragma unroll
            for (int nt = 0; nt < 4; nt++) {
                int mrow = m0 + wm * 64 + mt * 16 + r;
                int col = n0 + wn * 32 + (nt >> 1) * 16 + (nt & 1) * 8 + 2 * q;
                *(float2*)&out[(size_t)mrow * kE + col] =
                    make_float2(c[mt][nt][0], c[mt][nt][1]);
                *(float2*)&out[(size_t)(mrow + 8) * kE + col] =
                    make_float2(c[mt][nt][2], c[mt][nt][3]);
            }
    } else {
        const int which = (n0 >> 10);
#pragma unroll
        for (int mt = 0; mt < 4; mt++)
#pragma unroll
            for (int nt = 0; nt < 4; nt++) {
                int mrow = m0 + wm * 64 + mt * 16 + r;
                int n = n0 + wn * 32 + (nt >> 1) * 16 + (nt & 1) * 8 + 2 * q;
                int h = (n >> 6) & 15;
                int dl = n & 63;
                int b = mrow >> 11, s = mrow & (kS - 1);
                int bh = b * kH + h;
                if (which == 2) {
                    size_t base = ((size_t)(bh * kD + dl)) * kS;
                    g_vt[base + s] = tf32r(c[mt][nt][0]);
                    g_vt[base + kS + s] = tf32r(c[mt][nt][1]);
                    g_vt[base + s + 8] = tf32r(c[mt][nt][2]);
                    g_vt[base + kS + s + 8] = tf32r(c[mt][nt][3]);
                } else {
                    int i = dl >> 1;
                    float inv = expf(-(float)i * (kLN1e4 / 32.0f));
                    float sn0, cs0, sn1, cs1;
                    sincosf((float)s * inv, &sn0, &cs0);
                    sincosf((float)(s + 8) * inv, &sn1, &cs1);
                    float y0 = c[mt][nt][0] * cs0 - c[mt][nt][1] * sn0;
                    float y1 = c[mt][nt][0] * sn0 + c[mt][nt][1] * cs0;
                    float z0 = c[mt][nt][2] * cs1 - c[mt][nt][3] * sn1;
                    float z1 = c[mt][nt][2] * sn1 + c[mt][nt][3] * cs1;
                    float* dst;
                    if (which == 0) {
                        y0 *= kScale; y1 *= kScale; z0 *= kScale; z1 *= kScale;
                        dst = g_q;
                    } else {
                        dst = g_k;
                    }
                    size_t base = ((size_t)(bh * kS + s)) * kD + dl;
                    *(float2*)&dst[base] = make_float2(tf32r(y0), tf32r(y1));
                    *(float2*)&dst[base + 8 * kD] = make_float2(tf32r(z0), tf32r(z1));
                }
            }
    }
}

// ---------------- Flash attention: cp.async 2-stage pipeline ----------------
// grid: (16 q-tiles, 32 bh). block: 256 threads = 8 warps, 128 q rows, kv tile 64.
// dynamic smem: Ks[2][64][68] + Vs[2][64][68] = 69632 B.
#define ATTN_SMEM (4 * 64 * 68 * 4)
__global__ __launch_bounds__(256) void attn_tc() {
    extern __shared__ float sm[];
    float (*Ks)[64][68] = (float(*)[64][68])sm;            // [stage][kv][d]
    float (*Vs)[64][68] = (float(*)[64][68])(sm + 2 * 64 * 68);  // [stage][d][kv]

    const int t = threadIdx.x;
    const int w = t >> 5, lane = t & 31;
    const int r = lane >> 2, q = lane & 3;
    const int bh = blockIdx.y;
    const int q0 = blockIdx.x * 128;
    const float* qb = g_q + ((size_t)bh * kS + q0) * kD;
    const float* kb = g_k + (size_t)bh * kS * kD;
    const float* vtb = g_vt + (size_t)bh * kD * kS;

    // ---- Stage Q (128 rows) through Ks[0], extract scalar A-frags ----
    unsigned qa[8][4];
#pragma unroll 1
    for (int half = 0; half < 2; half++) {
        __syncthreads();
        const float4* qsrc = (const float4*)(qb + (size_t)half * 64 * kD);
#pragma unroll
        for (int j = 0; j < 4; j++) {
            int f4i = t + 256 * j;
            *(float4*)&Ks[0][f4i >> 4][(f4i & 15) * 4] = qsrc[f4i];
        }
        __syncthreads();
        if ((w >> 2) == half) {
            int m = 16 * (w & 3) + r;
#pragma unroll
            for (int kk = 0; kk < 8; kk++) {
                qa[kk][0] = fbits(Ks[0][m][kk * 8 + q]);
                qa[kk][1] = fbits(Ks[0][m + 8][kk * 8 + q]);
                qa[kk][2] = fbits(Ks[0][m][kk * 8 + 4 + q]);
                qa[kk][3] = fbits(Ks[0][m + 8][kk * 8 + 4 + q]);
            }
        }
    }
    __syncthreads();  // all Q frag reads done before prefetch overwrites Ks[0]

    // ---- cp.async prologue: tiles 0 and 1 ----
#pragma unroll 1
    for (int p = 0; p < 2; p++) {
        const float* ksrc = kb + (size_t)(p * 64) * kD;
#pragma unroll
        for (int j = 0; j < 4; j++) {
            int f4i = t + 256 * j;
            cp16(&Ks[p][f4i >> 4][(f4i & 15) * 4], ksrc + (size_t)f4i * 4);
        }
#pragma unroll
        for (int j = 0; j < 4; j++) {
            int row = (t >> 4) + 16 * j;
            cp16(&Vs[p][row][4 * (t & 15)],
                 vtb + (size_t)row * kS + p * 64 + 4 * (t & 15));
        }
        CP_COMMIT();
    }

    float m0v = -1e30f, m1v = -1e30f, l0 = 0.f, l1 = 0.f;
    float o[8][4];
#pragma unroll
    for (int i = 0; i < 8; i++)
#pragma unroll
        for (int j = 0; j < 4; j++) o[i][j] = 0.f;

    const int src0 = (lane & ~3) | (q >> 1);
    const int src2 = src0 + 2;

    for (int kt = 0; kt < 32; kt++) {
        if (kt == 31) { CP_WAIT(0); } else { CP_WAIT(1); }
        __syncthreads();  // tile kt resident; everyone past tile kt-1
        const int st = kt & 1;

        // S = Q K^T  (c[nt]: cols 8nt + {2q,2q+1}; rows 16w+r / +8)
        float c[8][4];
#pragma unroll
        for (int i = 0; i < 8; i++)
#pragma unroll
            for (int j = 0; j < 4; j++) c[i][j] = 0.f;
#pragma unroll
        for (int kk = 0; kk < 8; kk++) {
#pragma unroll
            for (int nt = 0; nt < 8; nt++) {
                unsigned bf[2];
                bf[0] = fbits(Ks[st][8 * nt + r][kk * 8 + q]);
                bf[1] = fbits(Ks[st][8 * nt + r][kk * 8 + 4 + q]);
                mma8(c[nt], qa[kk], bf);
            }
        }

        // online softmax
        float mt0 = -1e30f, mt1 = -1e30f;
#pragma unroll
        for (int nt = 0; nt < 8; nt++) {
            mt0 = fmaxf(mt0, fmaxf(c[nt][0], c[nt][1]));
            mt1 = fmaxf(mt1, fmaxf(c[nt][2], c[nt][3]));
        }
        mt0 = fmaxf(mt0, __shfl_xor_sync(0xffffffffu, mt0, 1));
        mt0 = fmaxf(mt0, __shfl_xor_sync(0xffffffffu, mt0, 2));
        mt1 = fmaxf(mt1, __shfl_xor_sync(0xffffffffu, mt1, 1));
        mt1 = fmaxf(mt1, __shfl_xor_sync(0xffffffffu, mt1, 2));
        float mn0 = fmaxf(m0v, mt0), mn1 = fmaxf(m1v, mt1);
        float cor0 = __expf(m0v - mn0), cor1 = __expf(m1v - mn1);
        m0v = mn0; m1v = mn1;
        float rs0 = 0.f, rs1 = 0.f;
#pragma unroll
        for (int nt = 0; nt < 8; nt++) {
            c[nt][0] = __expf(c[nt][0] - mn0); rs0 += c[nt][0];
            c[nt][1] = __expf(c[nt][1] - mn0); rs0 += c[nt][1];
            c[nt][2] = __expf(c[nt][2] - mn1); rs1 += c[nt][2];
            c[nt][3] = __expf(c[nt][3] - mn1); rs1 += c[nt][3];
        }
        rs0 += __shfl_xor_sync(0xffffffffu, rs0, 1);
        rs0 += __shfl_xor_sync(0xffffffffu, rs0, 2);
        rs1 += __shfl_xor_sync(0xffffffffu, rs1, 1);
        rs1 += __shfl_xor_sync(0xffffffffu, rs1, 2);
        l0 = l0 * cor0 + rs0;
        l1 = l1 * cor1 + rs1;
#pragma unroll
        for (int nt = 0; nt < 8; nt++) {
            o[nt][0] *= cor0; o[nt][1] *= cor0;
            o[nt][2] *= cor1; o[nt][3] *= cor1;
        }

        // O += P V
#pragma unroll
        for (int kk = 0; kk < 8; kk++) {
            float u0 = __shfl_sync(0xffffffffu, c[kk][0], src0);
            float u1 = __shfl_sync(0xffffffffu, c[kk][1], src0);
            float u2 = __shfl_sync(0xffffffffu, c[kk][2], src0);
            float u3 = __shfl_sync(0xffffffffu, c[kk][3], src0);
            float v0 = __shfl_sync(0xffffffffu, c[kk][0], src2);
            float v1 = __shfl_sync(0xffffffffu, c[kk][1], src2);
            float v2 = __shfl_sync(0xffffffffu, c[kk][2], src2);
            float v3 = __shfl_sync(0xffffffffu, c[kk][3], src2);
            unsigned pa[4];
            pa[0] = f2tf((q & 1) ? u1 : u0);
            pa[1] = f2tf((q & 1) ? u3 : u2);
            pa[2] = f2tf((q & 1) ? v1 : v0);
            pa[3] = f2tf((q & 1) ? v3 : v2);
#pragma unroll
            for (int nt = 0; nt < 8; nt++) {
                unsigned bf[2];
                bf[0] = fbits(Vs[st][8 * nt + r][kk * 8 + q]);
                bf[1] = fbits(Vs[st][8 * nt + r][kk * 8 + 4 + q]);
                mma8(o[nt], pa, bf);
            }
        }

        __syncthreads();  // stage st fully consumed
        if (kt + 2 < 32) {
            const int p = kt + 2;
            const float* ksrc = kb + (size_t)(p * 64) * kD;
#pragma unroll
            for (int j = 0; j < 4; j++) {
                int f4i = t + 256 * j;
                cp16(&Ks[st][f4i >> 4][(f4i & 15) * 4], ksrc + (size_t)f4i * 4);
            }
#pragma unroll
            for (int j = 0; j < 4; j++) {
                int row = (t >> 4) + 16 * j;
                cp16(&Vs[st][row][4 * (t & 15)],
                     vtb + (size_t)row * kS + p * 64 + 4 * (t & 15));
            }
            CP_COMMIT();
        }
    }

    // epilogue: normalize and store to ctx [b][s][h*64+d]
    float il0 = 1.f / l0, il1 = 1.f / l1;
    const int b = bh >> 4, h = bh & 15;
    const int row0 = q0 + 16 * w + r;
    float* dst = g_ctx + ((size_t)(b * kS + row0)) * kE + h * kD;
#pragma unroll
    for (int nt = 0; nt < 8; nt++) {
        *(float2*)&dst[8 * nt + 2 * q] =
            make_float2(o[nt][0] * il0, o[nt][1] * il0);
        *(float2*)&dst[8 * kE + 8 * nt + 2 * q] =
            make_float2(o[nt][2] * il1, o[nt][3] * il1);
    }
}

extern "C" void kernel_launch(void* const* d_in, const int* in_sizes, int n_in,
                              void* d_out, int out_size) {
    const float* query = (const float*)d_in[0];
    // d_in[1] (key), d_in[2] (value) are unused by the reference computation
    const float* w_qkv = (const float*)d_in[3];
    const float* w_out = (const float*)d_in[4];
    float* out = (float*)d_out;

    cudaFuncSetAttribute(attn_tc, cudaFuncAttributeMaxDynamicSharedMemorySize,
                         ATTN_SMEM);

    gemm_tc<<<dim3(32, 24), 256>>>(query, w_qkv, nullptr, 0);
    attn_tc<<<dim3(16, 32), 256, ATTN_SMEM>>>();
    gemm_tc<<<dim3(32, 8), 256>>>(nullptr, w_out, out, 1);
}

// round 7
// speedup vs baseline: 1.9295x; 1.2430x over previous
#include <cuda_runtime.h>
#include <cuda_fp16.h>
#include <math.h>

// Problem constants
#define kB 2
#define kS 2048
#define kE 1024
#define kH 16
#define kD 64
#define kBH (kB * kH)
#define kScale 0.125f
#define kLN1e4 9.210340371976184f

// Scratch (device globals: allocation-free)
static __device__ __half g_qh[kBH * kS * kD];   // [bh][s][d] (rope+scale)
static __device__ __half g_kh[kBH * kS * kD];   // [bh][s][d] (rope)
static __device__ __half g_vth[kBH * kD * kS];  // [bh][d][s] (transposed V)
static __device__ __half g_ctxh[kB * kS * kE];  // [b][s][h*64+d]

// ---------------- helpers ----------------
__device__ __forceinline__ unsigned packh2(float lo, float hi) {
    __half2 h = __floats2half2_rn(lo, hi);
    return *(unsigned*)&h;
}
__device__ __forceinline__ unsigned smem_u32(const void* p) {
    unsigned r;
    asm("{ .reg .u64 t; cvta.to.shared.u64 t, %1; cvt.u32.u64 %0, t; }"
        : "=r"(r) : "l"(p));
    return r;
}
__device__ __forceinline__ void ldsm4(unsigned* f, unsigned addr) {
    asm volatile("ldmatrix.sync.aligned.m8n8.x4.shared.b16 {%0,%1,%2,%3}, [%4];"
                 : "=r"(f[0]), "=r"(f[1]), "=r"(f[2]), "=r"(f[3]) : "r"(addr));
}
__device__ __forceinline__ void cp16(void* dst, const void* src) {
    asm volatile("cp.async.cg.shared.global [%0], [%1], 16;" ::
                     "r"(smem_u32(dst)), "l"(src) : "memory");
}
#define CP_COMMIT() asm volatile("cp.async.commit_group;" ::: "memory")
#define CP_WAIT(n) asm volatile("cp.async.wait_group %0;" :: "n"(n) : "memory")

// D(16x8,f32) += A(16x16,f16) * B(16x8,f16)
__device__ __forceinline__ void mma16h(float* c, const unsigned* a, unsigned b0,
                                       unsigned b1) {
    asm volatile(
        "mma.sync.aligned.m16n8k16.row.col.f32.f16.f16.f32 "
        "{%0,%1,%2,%3}, {%4,%5,%6,%7}, {%8,%9}, {%0,%1,%2,%3};"
        : "+f"(c[0]), "+f"(c[1]), "+f"(c[2]), "+f"(c[3])
        : "r"(a[0]), "r"(a[1]), "r"(a[2]), "r"(a[3]), "r"(b0), "r"(b1));
}

// ---------------- fp16 tensor-core GEMM: out[m,n] = sum_k A[m,k]*W[n,k] -------
// BM=128, BN=128, BK=32, double-buffered. 256 threads = 8 warps (2m x 4n),
// warp tile 64x32.  mode 0: A=query(f32), W=w_qkv -> g_qh/g_kh/g_vth (RoPE
// fused). mode 1: A=g_ctxh(f16), W=w_out -> out(f32).
#define GBK 32
#define GPADH 40  // halves per row (32 data + 8 pad); 80B stride, conflict-free
__global__ __launch_bounds__(256) void gemm_h(const float* __restrict__ Ain,
                                              const float* __restrict__ W,
                                              float* __restrict__ out, int mode) {
    __shared__ __half As[2][128][GPADH];
    __shared__ __half Ws[2][128][GPADH];

    const int t = threadIdx.x;
    const int w = t >> 5, lane = t & 31;
    const int r = lane >> 2, q = lane & 3;
    const int wm = w >> 2, wn = w & 3;
    const int m0 = blockIdx.x * 128;
    const int n0 = blockIdx.y * 128;

    const int row = t >> 1;          // 0..127
    const int seg = (t & 1) * 16;    // halves within BK

    float c[4][4][4];
#pragma unroll
    for (int i = 0; i < 4; i++)
#pragma unroll
        for (int j = 0; j < 4; j++)
#pragma unroll
            for (int v = 0; v < 4; v++) c[i][j][v] = 0.f;

    const float* Af = Ain + (size_t)(m0 + row) * kE + seg;       // mode 0
    const __half* Ah = g_ctxh + (size_t)(m0 + row) * kE + seg;   // mode 1
    const float* Wf = W + (size_t)(n0 + row) * kE + seg;

    // staged registers for next chunk
    float4 fa[4], fw[4];
    uint4 ua[2];
    if (mode == 0) {
#pragma unroll
        for (int i = 0; i < 4; i++) fa[i] = *(const float4*)(Af + 4 * i);
    } else {
        ua[0] = *(const uint4*)(Ah);
        ua[1] = *(const uint4*)(Ah + 8);
    }
#pragma unroll
    for (int i = 0; i < 4; i++) fw[i] = *(const float4*)(Wf + 4 * i);

    // store stage 0
    {
        if (mode == 0) {
            unsigned tmp[8];
#pragma unroll
            for (int i = 0; i < 4; i++) {
                tmp[2 * i] = packh2(fa[i].x, fa[i].y);
                tmp[2 * i + 1] = packh2(fa[i].z, fa[i].w);
            }
            *(uint4*)&As[0][row][seg] = *(uint4*)&tmp[0];
            *(uint4*)&As[0][row][seg + 8] = *(uint4*)&tmp[4];
        } else {
            *(uint4*)&As[0][row][seg] = ua[0];
            *(uint4*)&As[0][row][seg + 8] = ua[1];
        }
        unsigned tw[8];
#pragma unroll
        for (int i = 0; i < 4; i++) {
            tw[2 * i] = packh2(fw[i].x, fw[i].y);
            tw[2 * i + 1] = packh2(fw[i].z, fw[i].w);
        }
        *(uint4*)&Ws[0][row][seg] = *(uint4*)&tw[0];
        *(uint4*)&Ws[0][row][seg + 8] = *(uint4*)&tw[4];
    }
    __syncthreads();

    // ldmatrix lane addresses (stage 0)
    const unsigned stageSz = 128 * GPADH * 2;  // bytes
    unsigned aoff[4], woff[2];
#pragma unroll
    for (int mt = 0; mt < 4; mt++)
        aoff[mt] = smem_u32(&As[0][wm * 64 + mt * 16 + (lane & 15)][(lane >> 4) * 8]);
#pragma unroll
    for (int ng = 0; ng < 2; ng++)
        woff[ng] = smem_u32(&Ws[0][wn * 32 + ng * 16 + (lane & 15)][(lane >> 4) * 8]);

    const int NIT = kE / GBK;  // 32
    for (int it = 0; it < NIT; it++) {
        const int cur = it & 1;
        if (it + 1 < NIT) {
            const int k0 = (it + 1) * GBK;
            if (mode == 0) {
#pragma unroll
                for (int i = 0; i < 4; i++) fa[i] = *(const float4*)(Af + k0 + 4 * i);
            } else {
                ua[0] = *(const uint4*)(Ah + k0);
                ua[1] = *(const uint4*)(Ah + k0 + 8);
            }
#pragma unroll
            for (int i = 0; i < 4; i++) fw[i] = *(const float4*)(Wf + k0 + 4 * i);
        }
        const unsigned sOf = cur ? stageSz : 0u;
#pragma unroll
        for (int kk = 0; kk < 2; kk++) {  // two k16 steps per BK=32
            unsigned af[4][4], bw[2][4];
#pragma unroll
            for (int mt = 0; mt < 4; mt++) ldsm4(af[mt], aoff[mt] + sOf + kk * 32);
#pragma unroll
            for (int ng = 0; ng < 2; ng++) ldsm4(bw[ng], woff[ng] + sOf + kk * 32);
#pragma unroll
            for (int mt = 0; mt < 4; mt++)
#pragma unroll
                for (int ng = 0; ng < 2; ng++) {
                    mma16h(c[mt][2 * ng], af[mt], bw[ng][0], bw[ng][2]);
                    mma16h(c[mt][2 * ng + 1], af[mt], bw[ng][1], bw[ng][3]);
                }
        }
        if (it + 1 < NIT) {
            const int nxt = cur ^ 1;
            if (mode == 0) {
                unsigned tmp[8];
#pragma unroll
                for (int i = 0; i < 4; i++) {
                    tmp[2 * i] = packh2(fa[i].x, fa[i].y);
                    tmp[2 * i + 1] = packh2(fa[i].z, fa[i].w);
                }
                *(uint4*)&As[nxt][row][seg] = *(uint4*)&tmp[0];
                *(uint4*)&As[nxt][row][seg + 8] = *(uint4*)&tmp[4];
            } else {
                *(uint4*)&As[nxt][row][seg] = ua[0];
                *(uint4*)&As[nxt][row][seg + 8] = ua[1];
            }
            unsigned tw[8];
#pragma unroll
            for (int i = 0; i < 4; i++) {
                tw[2 * i] = packh2(fw[i].x, fw[i].y);
                tw[2 * i + 1] = packh2(fw[i].z, fw[i].w);
            }
            *(uint4*)&Ws[nxt][row][seg] = *(uint4*)&tw[0];
            *(uint4*)&Ws[nxt][row][seg + 8] = *(uint4*)&tw[4];
        }
        __syncthreads();
    }

    // ---------------- epilogue ----------------
    if (mode == 1) {
#pragma unroll
        for (int mt = 0; mt < 4; mt++)
#pragma unroll
            for (int nt = 0; nt < 4; nt++) {
                int mrow = m0 + wm * 64 + mt * 16 + r;
                int col = n0 + wn * 32 + 8 * nt + 2 * q;
                *(float2*)&out[(size_t)mrow * kE + col] =
                    make_float2(c[mt][nt][0], c[mt][nt][1]);
                *(float2*)&out[(size_t)(mrow + 8) * kE + col] =
                    make_float2(c[mt][nt][2], c[mt][nt][3]);
            }
    } else {
        const int which = n0 >> 10;  // 0=q 1=k 2=v (128 | 1024)
#pragma unroll
        for (int mt = 0; mt < 4; mt++)
#pragma unroll
            for (int nt = 0; nt < 4; nt++) {
                int mrow = m0 + wm * 64 + mt * 16 + r;
                int n = n0 + wn * 32 + 8 * nt + 2 * q;
                int h = (n >> 6) & 15;
                int dl = n & 63;
                int b = mrow >> 11, s = mrow & (kS - 1);
                int bh = b * kH + h;
                if (which == 2) {
                    size_t base = ((size_t)(bh * kD + dl)) * kS;
                    g_vth[base + s] = __float2half_rn(c[mt][nt][0]);
                    g_vth[base + kS + s] = __float2half_rn(c[mt][nt][1]);
                    g_vth[base + s + 8] = __float2half_rn(c[mt][nt][2]);
                    g_vth[base + kS + s + 8] = __float2half_rn(c[mt][nt][3]);
                } else {
                    int i = dl >> 1;
                    float inv = expf(-(float)i * (kLN1e4 / 32.0f));
                    float sn0, cs0, sn1, cs1;
                    sincosf((float)s * inv, &sn0, &cs0);
                    sincosf((float)(s + 8) * inv, &sn1, &cs1);
                    float y0 = c[mt][nt][0] * cs0 - c[mt][nt][1] * sn0;
                    float y1 = c[mt][nt][0] * sn0 + c[mt][nt][1] * cs0;
                    float z0 = c[mt][nt][2] * cs1 - c[mt][nt][3] * sn1;
                    float z1 = c[mt][nt][2] * sn1 + c[mt][nt][3] * cs1;
                    __half* dst;
                    if (which == 0) {
                        y0 *= kScale; y1 *= kScale; z0 *= kScale; z1 *= kScale;
                        dst = g_qh;
                    } else {
                        dst = g_kh;
                    }
                    size_t base = ((size_t)(bh * kS + s)) * kD + dl;
                    *(unsigned*)&dst[base] = packh2(y0, y1);
                    *(unsigned*)&dst[base + 8 * kD] = packh2(z0, z1);
                }
            }
    }
}

// ---------------- Flash attention: fp16 MMA + cp.async 2-stage ----------------
// grid: (16 q-tiles, 32 bh). block: 256 threads = 8 warps, 128 q rows, kv tile 64.
__global__ __launch_bounds__(256) void attn_h() {
    __shared__ __half Ks[2][64][72];  // [stage][kv][d]   (also Q staging)
    __shared__ __half Vs[2][64][72];  // [stage][d][kv]

    const int t = threadIdx.x;
    const int w = t >> 5, lane = t & 31;
    const int r = lane >> 2, q = lane & 3;
    const int bh = blockIdx.y;
    const int q0 = blockIdx.x * 128;
    const __half* qb = g_qh + ((size_t)bh * kS + q0) * kD;
    const __half* kb = g_kh + (size_t)bh * kS * kD;
    const __half* vtb = g_vth + (size_t)bh * kD * kS;

    // ---- Stage Q (128 rows) through Ks[0], extract A-frags (4 k16 chunks) ----
    unsigned qa[4][4];
#pragma unroll 1
    for (int half = 0; half < 2; half++) {
        __syncthreads();
        const uint4* qsrc = (const uint4*)(qb + (size_t)half * 64 * kD);
#pragma unroll
        for (int j = 0; j < 2; j++) {
            int idx = t + 256 * j;
            *(uint4*)&Ks[0][idx >> 3][(idx & 7) * 8] = qsrc[idx];
        }
        __syncthreads();
        if ((w >> 2) == half) {
            int m = 16 * (w & 3) + r;
#pragma unroll
            for (int kk = 0; kk < 4; kk++) {
                qa[kk][0] = *(const unsigned*)&Ks[0][m][16 * kk + 2 * q];
                qa[kk][1] = *(const unsigned*)&Ks[0][m + 8][16 * kk + 2 * q];
                qa[kk][2] = *(const unsigned*)&Ks[0][m][16 * kk + 8 + 2 * q];
                qa[kk][3] = *(const unsigned*)&Ks[0][m + 8][16 * kk + 8 + 2 * q];
            }
        }
    }
    __syncthreads();  // Q reads done before prefetch overwrites Ks[0]

    // ---- cp.async prologue: tiles 0 and 1 ----
#pragma unroll 1
    for (int p = 0; p < 2; p++) {
#pragma unroll
        for (int j = 0; j < 2; j++) {
            int idx = t + 256 * j;
            int rw = idx >> 3, c8 = (idx & 7) * 8;
            cp16(&Ks[p][rw][c8], kb + (size_t)(p * 64 + rw) * kD + c8);
            cp16(&Vs[p][rw][c8], vtb + (size_t)rw * kS + p * 64 + c8);
        }
        CP_COMMIT();
    }

    float m0v = -1e30f, m1v = -1e30f, l0 = 0.f, l1 = 0.f;
    float o[8][4];
#pragma unroll
    for (int i = 0; i < 8; i++)
#pragma unroll
        for (int j = 0; j < 4; j++) o[i][j] = 0.f;

    for (int kt = 0; kt < 32; kt++) {
        if (kt == 31) { CP_WAIT(0); } else { CP_WAIT(1); }
        __syncthreads();
        const int st = kt & 1;

        // S = Q K^T  (c[nt]: cols 8nt + {2q,2q+1}; rows 16w+r / +8)
        float c[8][4];
#pragma unroll
        for (int i = 0; i < 8; i++)
#pragma unroll
            for (int j = 0; j < 4; j++) c[i][j] = 0.f;
#pragma unroll
        for (int kk = 0; kk < 4; kk++) {
#pragma unroll
            for (int nt = 0; nt < 8; nt++) {
                unsigned b0 = *(const unsigned*)&Ks[st][8 * nt + r][16 * kk + 2 * q];
                unsigned b1 =
                    *(const unsigned*)&Ks[st][8 * nt + r][16 * kk + 8 + 2 * q];
                mma16h(c[nt], qa[kk], b0, b1);
            }
        }

        // online softmax
        float mt0 = -1e30f, mt1 = -1e30f;
#pragma unroll
        for (int nt = 0; nt < 8; nt++) {
            mt0 = fmaxf(mt0, fmaxf(c[nt][0], c[nt][1]));
            mt1 = fmaxf(mt1, fmaxf(c[nt][2], c[nt][3]));
        }
        mt0 = fmaxf(mt0, __shfl_xor_sync(0xffffffffu, mt0, 1));
        mt0 = fmaxf(mt0, __shfl_xor_sync(0xffffffffu, mt0, 2));
        mt1 = fmaxf(mt1, __shfl_xor_sync(0xffffffffu, mt1, 1));
        mt1 = fmaxf(mt1, __shfl_xor_sync(0xffffffffu, mt1, 2));
        float mn0 = fmaxf(m0v, mt0), mn1 = fmaxf(m1v, mt1);
        float cor0 = __expf(m0v - mn0), cor1 = __expf(m1v - mn1);
        m0v = mn0; m1v = mn1;
        float rs0 = 0.f, rs1 = 0.f;
#pragma unroll
        for (int nt = 0; nt < 8; nt++) {
            c[nt][0] = __expf(c[nt][0] - mn0); rs0 += c[nt][0];
            c[nt][1] = __expf(c[nt][1] - mn0); rs0 += c[nt][1];
            c[nt][2] = __expf(c[nt][2] - mn1); rs1 += c[nt][2];
            c[nt][3] = __expf(c[nt][3] - mn1); rs1 += c[nt][3];
        }
        rs0 += __shfl_xor_sync(0xffffffffu, rs0, 1);
        rs0 += __shfl_xor_sync(0xffffffffu, rs0, 2);
        rs1 += __shfl_xor_sync(0xffffffffu, rs1, 1);
        rs1 += __shfl_xor_sync(0xffffffffu, rs1, 2);
        l0 = l0 * cor0 + rs0;
        l1 = l1 * cor1 + rs1;
#pragma unroll
        for (int nt = 0; nt < 8; nt++) {
            o[nt][0] *= cor0; o[nt][1] *= cor0;
            o[nt][2] *= cor1; o[nt][3] *= cor1;
        }

        // pack P to half2 — A-frags come straight from this lane's registers
        unsigned ph0[8], ph1[8];
#pragma unroll
        for (int nt = 0; nt < 8; nt++) {
            ph0[nt] = packh2(c[nt][0], c[nt][1]);
            ph1[nt] = packh2(c[nt][2], c[nt][3]);
        }

        // O += P V (no shuffles: k16 chunk kk uses cols 16kk+2q & +8 = own regs)
#pragma unroll
        for (int kk = 0; kk < 4; kk++) {
            unsigned a[4] = {ph0[2 * kk], ph1[2 * kk], ph0[2 * kk + 1],
                             ph1[2 * kk + 1]};
#pragma unroll
            for (int nt = 0; nt < 8; nt++) {
                unsigned b0 = *(const unsigned*)&Vs[st][8 * nt + r][16 * kk + 2 * q];
                unsigned b1 =
                    *(const unsigned*)&Vs[st][8 * nt + r][16 * kk + 8 + 2 * q];
                mma16h(o[nt], a, b0, b1);
            }
        }

        __syncthreads();  // stage st fully consumed
        if (kt + 2 < 32) {
            const int p = kt + 2;
#pragma unroll
            for (int j = 0; j < 2; j++) {
                int idx = t + 256 * j;
                int rw = idx >> 3, c8 = (idx & 7) * 8;
                cp16(&Ks[st][rw][c8], kb + (size_t)(p * 64 + rw) * kD + c8);
                cp16(&Vs[st][rw][c8], vtb + (size_t)rw * kS + p * 64 + c8);
            }
            CP_COMMIT();
        }
    }

    // epilogue: normalize, store ctx as half [b][s][h*64+d]
    float il0 = 1.f / l0, il1 = 1.f / l1;
    const int b = bh >> 4, h = bh & 15;
    const int row0 = q0 + 16 * w + r;
    __half* dst = g_ctxh + ((size_t)(b * kS + row0)) * kE + h * kD;
#pragma unroll
    for (int nt = 0; nt < 8; nt++) {
        *(unsigned*)&dst[8 * nt + 2 * q] = packh2(o[nt][0] * il0, o[nt][1] * il0);
        *(unsigned*)&dst[8 * kE + 8 * nt + 2 * q] =
            packh2(o[nt][2] * il1, o[nt][3] * il1);
    }
}

extern "C" void kernel_launch(void* const* d_in, const int* in_sizes, int n_in,
                              void* d_out, int out_size) {
    const float* query = (const float*)d_in[0];
    // d_in[1] (key), d_in[2] (value) are unused by the reference computation
    const float* w_qkv = (const float*)d_in[3];
    const float* w_out = (const float*)d_in[4];
    float* out = (float*)d_out;

    gemm_h<<<dim3(32, 24), 256>>>(query, w_qkv, nullptr, 0);
    attn_h<<<dim3(16, 32), 256>>>();
    gemm_h<<<dim3(32, 8), 256>>>(nullptr, w_out, out, 1);
}